// round 12
// baseline (speedup 1.0000x reference)
#include <cuda_runtime.h>
#include <cuda_bf16.h>
#include <cuda_fp16.h>
#include <cstdint>

#define NN 50000
#define NE 800000
#define ET 850000   // NE + NN self loops
#define D1 256      // heads(4) * h1(64)
#define D2 128

// ---------------- device scratch (static; no runtime allocation) ----------------
__device__ __align__(16) __half g_xh1h[NN * D1];   // X @ W1 (fp16)
__device__ __align__(16) __half g_xh2h[NN * D2];   // H1 @ W2 (fp16)
__device__ __align__(16) __half g_xf16[NN * 64];    // X as fp16 (gemm1 A)
__device__ __align__(16) __half g_h1f16[NN * D1];   // H1 as fp16 (gemm2 A)
__device__ __align__(16) float g_as1[NN * 4];
__device__ __align__(16) float g_ad1[NN * 4];
__device__ float g_as2[NN];
__device__ float g_ad2[NN];
__device__ int g_deg[NN];
__device__ int g_rowptr[NN + 1];
__device__ int g_rank[ET];
__device__ int g_esrc[ET];
// transposed fp16 weights: Wt[n][k]
__device__ __align__(16) __half g_wt1f[D1 * 64];
__device__ __align__(16) __half g_wt2f[D2 * D1];

__device__ __forceinline__ int esrc_of(const int* __restrict__ ei, int e) {
    return e < NE ? ei[e] : e - NE;
}
__device__ __forceinline__ int edst_of(const int* __restrict__ ei, int e) {
    return e < NE ? ei[NE + e] : e - NE;
}
__device__ __forceinline__ float lrelu(float x) { return x > 0.f ? x : 0.2f * x; }

// ---------------- fused prep: zero_deg + X fp16 + W transposes + edge count ----------------
__global__ __launch_bounds__(256) void k_prep_count(const float* __restrict__ X,
                                                    const float* __restrict__ W1,
                                                    const float* __restrict__ W2,
                                                    const int* __restrict__ ei) {
    int i = blockIdx.x * 256 + threadIdx.x;
    if (i < NN) g_deg[i] = 0;
    if (i < NN * 16) {
        float4 v = ((const float4*)X)[i];
        __half2 h0 = __floats2half2_rn(v.x, v.y);
        __half2 h1 = __floats2half2_rn(v.z, v.w);
        ((uint2*)g_xf16)[i] = make_uint2(*(uint32_t*)&h0, *(uint32_t*)&h1);
    }
    if (i < 64 * D1) {
        int k = i / D1, n = i % D1;
        g_wt1f[n * 64 + k] = __float2half(W1[i]);
    }
    if (i < D1 * D2) {
        int k = i / D2, n = i % D2;
        g_wt2f[n * D1 + k] = __float2half(W2[i]);
    }
}

__global__ void k_count(const int* __restrict__ ei) {
    int e = blockIdx.x * 256 + threadIdx.x;
    if (e < ET) {
        int r = atomicAdd(&g_deg[edst_of(ei, e)], 1);
        g_rank[e] = r;
    }
}

// ---------------- fused exclusive scan of g_deg -> g_rowptr, single block ----------------
#define SCHUNK 49   // 1024 * 49 = 50176 >= NN
__global__ __launch_bounds__(1024) void k_scan_all() {
    __shared__ int s[1024];
    int t = threadIdx.x;
    int base = t * SCHUNK;
    int loc[SCHUNK];
    int sum = 0;
    #pragma unroll
    for (int j = 0; j < SCHUNK; j++) {
        int idx = base + j;
        int v = (idx < NN) ? g_deg[idx] : 0;
        loc[j] = sum;          // exclusive within chunk
        sum += v;
    }
    s[t] = sum;
    __syncthreads();
    // block inclusive scan of chunk totals
    #pragma unroll
    for (int off = 1; off < 1024; off <<= 1) {
        int x = (t >= off) ? s[t - off] : 0;
        __syncthreads();
        s[t] += x;
        __syncthreads();
    }
    int chunk_off = (t > 0) ? s[t - 1] : 0;   // exclusive prefix of this chunk
    #pragma unroll
    for (int j = 0; j < SCHUNK; j++) {
        int idx = base + j;
        if (idx < NN) g_rowptr[idx] = chunk_off + loc[j];
    }
    if (t == 1023) g_rowptr[NN] = ET;
}

__global__ void k_fill(const int* __restrict__ ei) {
    int e = blockIdx.x * 256 + threadIdx.x;
    if (e < ET) {
        int d = edst_of(ei, e);
        int s = esrc_of(ei, e);
        g_esrc[g_rowptr[d] + g_rank[e]] = s;
    }
}

// ---------------- HMMA fp16 GEMM, 3-stage cp.async pipeline, fp16 out ----------------
#define KC 32
#define ASTR 40
#define TILE_ELEMS (128 * ASTR)
#define NSTAGE 3

__device__ __forceinline__ void ldsm4h(uint32_t& r0, uint32_t& r1, uint32_t& r2, uint32_t& r3,
                                       const __half* p) {
    uint32_t a = (uint32_t)__cvta_generic_to_shared(p);
    asm volatile("ldmatrix.sync.aligned.m8n8.x4.shared.b16 {%0,%1,%2,%3}, [%4];"
                 : "=r"(r0), "=r"(r1), "=r"(r2), "=r"(r3) : "r"(a));
}
__device__ __forceinline__ void mmaf16(float* d, uint32_t a0, uint32_t a1, uint32_t a2,
                                       uint32_t a3, uint32_t b0, uint32_t b1) {
    asm volatile(
        "mma.sync.aligned.m16n8k16.row.col.f32.f16.f16.f32 "
        "{%0,%1,%2,%3}, {%4,%5,%6,%7}, {%8,%9}, {%0,%1,%2,%3};"
        : "+f"(d[0]), "+f"(d[1]), "+f"(d[2]), "+f"(d[3])
        : "r"(a0), "r"(a1), "r"(a2), "r"(a3), "r"(b0), "r"(b1));
}
__device__ __forceinline__ void cpa16h(__half* dst, const __half* src) {
    uint32_t d = (uint32_t)__cvta_generic_to_shared(dst);
    asm volatile("cp.async.cg.shared.global [%0], [%1], 16;" :: "r"(d), "l"(src));
}

template<int KTOT>
__global__ __launch_bounds__(256, 2) void k_gemm_f16(const __half* __restrict__ A,
                                                     const __half* __restrict__ Bt,
                                                     __half* __restrict__ C,
                                                     int M, int NCOL) {
    constexpr int NCH = KTOT / KC;
    extern __shared__ __half smh[];

    int tid = threadIdx.x;
    int wid = tid >> 5, lane = tid & 31;
    int g = lane >> 2, tig = lane & 3;
    int wm = (wid >> 2) * 64;
    int wn = (wid & 3) * 32;
    int bm = blockIdx.y * 128;
    int bn = blockIdx.x * 128;

    float acc[4][4][4];
    #pragma unroll
    for (int mt = 0; mt < 4; mt++)
        #pragma unroll
        for (int nt = 0; nt < 4; nt++)
            #pragma unroll
            for (int f = 0; f < 4; f++) acc[mt][nt][f] = 0.f;

    int a_r = lane & 15, a_c = (lane >> 4) * 8;
    int b_r = (lane >> 4) * 8 + (lane & 7), b_c = ((lane >> 3) & 1) * 8;

    int frow0 = tid >> 2, fcol = (tid & 3) * 8;
    int frow1 = (tid + 256) >> 2;

    auto fill = [&](int s, int c) {
        __half* s_a = smh + (s * 2 + 0) * TILE_ELEMS;
        __half* s_b = smh + (s * 2 + 1) * TILE_ELEMS;
        int kbase = c * KC;
        int ar0 = bm + frow0; if (ar0 >= M) ar0 = M - 1;
        int ar1 = bm + frow1; if (ar1 >= M) ar1 = M - 1;
        cpa16h(&s_a[frow0 * ASTR + fcol], &A[(size_t)ar0 * KTOT + kbase + fcol]);
        cpa16h(&s_a[frow1 * ASTR + fcol], &A[(size_t)ar1 * KTOT + kbase + fcol]);
        cpa16h(&s_b[frow0 * ASTR + fcol], &Bt[(size_t)(bn + frow0) * KTOT + kbase + fcol]);
        cpa16h(&s_b[frow1 * ASTR + fcol], &Bt[(size_t)(bn + frow1) * KTOT + kbase + fcol]);
        asm volatile("cp.async.commit_group;");
    };

    // prefill up to NSTAGE-1 stages
    #pragma unroll
    for (int c = 0; c < NSTAGE - 1 && c < NCH; c++)
        fill(c, c);

    for (int c = 0; c < NCH; c++) {
        int stage = c % NSTAGE;
        if (c + NSTAGE - 1 < NCH) {
            fill((c + NSTAGE - 1) % NSTAGE, c + NSTAGE - 1);
            asm volatile("cp.async.wait_group %0;" :: "n"(NSTAGE - 1));
        } else {
            asm volatile("cp.async.wait_group 0;");
        }
        __syncthreads();

        __half* s_a = smh + (stage * 2 + 0) * TILE_ELEMS;
        __half* s_b = smh + (stage * 2 + 1) * TILE_ELEMS;

        #pragma unroll
        for (int ks = 0; ks < KC; ks += 16) {
            uint32_t bf[4][2];
            #pragma unroll
            for (int p = 0; p < 2; p++)
                ldsm4h(bf[2*p][0], bf[2*p][1], bf[2*p+1][0], bf[2*p+1][1],
                       &s_b[(wn + p * 16 + b_r) * ASTR + ks + b_c]);
            #pragma unroll
            for (int mt = 0; mt < 4; mt++) {
                uint32_t a0, a1, a2, a3;
                ldsm4h(a0, a1, a2, a3, &s_a[(wm + mt * 16 + a_r) * ASTR + ks + a_c]);
                #pragma unroll
                for (int nt = 0; nt < 4; nt++)
                    mmaf16(acc[mt][nt], a0, a1, a2, a3, bf[nt][0], bf[nt][1]);
            }
        }
        __syncthreads();
    }

    // epilogue: fp16 stores
    #pragma unroll
    for (int mt = 0; mt < 4; mt++) {
        int r0 = bm + wm + mt * 16 + g;
        int r1 = r0 + 8;
        #pragma unroll
        for (int nt = 0; nt < 4; nt++) {
            int col = bn + wn + nt * 8 + 2 * tig;
            if (r0 < M) {
                __half2 h = __floats2half2_rn(acc[mt][nt][0], acc[mt][nt][1]);
                *(uint32_t*)&C[(size_t)r0 * NCOL + col] = *(uint32_t*)&h;
            }
            if (r1 < M) {
                __half2 h = __floats2half2_rn(acc[mt][nt][2], acc[mt][nt][3]);
                *(uint32_t*)&C[(size_t)r1 * NCOL + col] = *(uint32_t*)&h;
            }
        }
    }
}

// ---------------- attention logit vectors (fp16 features) ----------------
__global__ __launch_bounds__(256) void k_attn1(const float* __restrict__ att_s,
                                               const float* __restrict__ att_d) {
    int w = (blockIdx.x * blockDim.x + threadIdx.x) >> 5;
    int lane = threadIdx.x & 31;
    if (w >= NN) return;
    uint4 u = *(const uint4*)&g_xh1h[(size_t)w * D1 + lane * 8];
    float2 f0 = __half22float2(*(__half2*)&u.x);
    float2 f1 = __half22float2(*(__half2*)&u.y);
    float2 f2 = __half22float2(*(__half2*)&u.z);
    float2 f3 = __half22float2(*(__half2*)&u.w);
    const float4* ap = (const float4*)&att_s[lane * 8];
    float4 a0 = ap[0], a1 = ap[1];
    const float4* dp = (const float4*)&att_d[lane * 8];
    float4 d0 = dp[0], d1 = dp[1];
    float ss = f0.x*a0.x + f0.y*a0.y + f1.x*a0.z + f1.y*a0.w
             + f2.x*a1.x + f2.y*a1.y + f3.x*a1.z + f3.y*a1.w;
    float sd = f0.x*d0.x + f0.y*d0.y + f1.x*d0.z + f1.y*d0.w
             + f2.x*d1.x + f2.y*d1.y + f3.x*d1.z + f3.y*d1.w;
    #pragma unroll
    for (int m = 1; m < 8; m <<= 1) {
        ss += __shfl_xor_sync(0xffffffffu, ss, m);
        sd += __shfl_xor_sync(0xffffffffu, sd, m);
    }
    if ((lane & 7) == 0) {
        int h = lane >> 3;
        g_as1[w * 4 + h] = ss;
        g_ad1[w * 4 + h] = sd;
    }
}

__global__ __launch_bounds__(256) void k_attn2(const float* __restrict__ att_s,
                                               const float* __restrict__ att_d) {
    int w = (blockIdx.x * blockDim.x + threadIdx.x) >> 5;
    int lane = threadIdx.x & 31;
    if (w >= NN) return;
    uint2 u = *(const uint2*)&g_xh2h[(size_t)w * D2 + lane * 4];
    float2 f0 = __half22float2(*(__half2*)&u.x);
    float2 f1 = __half22float2(*(__half2*)&u.y);
    float4 a = *(const float4*)&att_s[lane * 4];
    float4 d = *(const float4*)&att_d[lane * 4];
    float ss = f0.x*a.x + f0.y*a.y + f1.x*a.z + f1.y*a.w;
    float sd = f0.x*d.x + f0.y*d.y + f1.x*d.z + f1.y*d.w;
    #pragma unroll
    for (int m = 1; m < 32; m <<= 1) {
        ss += __shfl_xor_sync(0xffffffffu, ss, m);
        sd += __shfl_xor_sync(0xffffffffu, sd, m);
    }
    if (lane == 0) { g_as2[w] = ss; g_ad2[w] = sd; }
}

// ---------------- layer-1 aggregation: single pass, fp16 gather, fp16 H1 out ----------------
__global__ __launch_bounds__(256) void k_agg1(const float* __restrict__ bias) {
    int w = (blockIdx.x * blockDim.x + threadIdx.x) >> 5;
    int lane = threadIdx.x & 31;
    if (w >= NN) return;
    int start = g_rowptr[w], end = g_rowptr[w + 1];
    int head = lane >> 3;
    float4 ad4 = *(const float4*)&g_ad1[w * 4];
    float adh = (head == 0) ? ad4.x : (head == 1) ? ad4.y : (head == 2) ? ad4.z : ad4.w;

    float den = 0.f;
    float acc0 = 0.f, acc1 = 0.f, acc2 = 0.f, acc3 = 0.f;
    float acc4 = 0.f, acc5 = 0.f, acc6 = 0.f, acc7 = 0.f;
    int p = start;
    for (; p + 1 < end; p += 2) {
        int sA = g_esrc[p];
        int sB = g_esrc[p + 1];
        float lA = g_as1[sA * 4 + head];
        float lB = g_as1[sB * 4 + head];
        uint4 ua = *(const uint4*)&g_xh1h[(size_t)sA * D1 + lane * 8];
        uint4 ub = *(const uint4*)&g_xh1h[(size_t)sB * D1 + lane * 8];
        float gA = __expf(lrelu(lA + adh));
        float gB = __expf(lrelu(lB + adh));
        den += gA + gB;
        float2 a0 = __half22float2(*(__half2*)&ua.x);
        float2 a1 = __half22float2(*(__half2*)&ua.y);
        float2 a2 = __half22float2(*(__half2*)&ua.z);
        float2 a3 = __half22float2(*(__half2*)&ua.w);
        float2 b0 = __half22float2(*(__half2*)&ub.x);
        float2 b1 = __half22float2(*(__half2*)&ub.y);
        float2 b2 = __half22float2(*(__half2*)&ub.z);
        float2 b3 = __half22float2(*(__half2*)&ub.w);
        acc0 += gA * a0.x + gB * b0.x; acc1 += gA * a0.y + gB * b0.y;
        acc2 += gA * a1.x + gB * b1.x; acc3 += gA * a1.y + gB * b1.y;
        acc4 += gA * a2.x + gB * b2.x; acc5 += gA * a2.y + gB * b2.y;
        acc6 += gA * a3.x + gB * b3.x; acc7 += gA * a3.y + gB * b3.y;
    }
    if (p < end) {
        int sA = g_esrc[p];
        float gA = __expf(lrelu(g_as1[sA * 4 + head] + adh));
        uint4 ua = *(const uint4*)&g_xh1h[(size_t)sA * D1 + lane * 8];
        den += gA;
        float2 a0 = __half22float2(*(__half2*)&ua.x);
        float2 a1 = __half22float2(*(__half2*)&ua.y);
        float2 a2 = __half22float2(*(__half2*)&ua.z);
        float2 a3 = __half22float2(*(__half2*)&ua.w);
        acc0 += gA * a0.x; acc1 += gA * a0.y;
        acc2 += gA * a1.x; acc3 += gA * a1.y;
        acc4 += gA * a2.x; acc5 += gA * a2.y;
        acc6 += gA * a3.x; acc7 += gA * a3.y;
    }
    float inv = 1.0f / den;
    const float4* bp = (const float4*)&bias[lane * 8];
    float4 b0 = bp[0], b1v = bp[1];
    __half2 o0 = __floats2half2_rn(acc0 * inv + b0.x,  acc1 * inv + b0.y);
    __half2 o1 = __floats2half2_rn(acc2 * inv + b0.z,  acc3 * inv + b0.w);
    __half2 o2 = __floats2half2_rn(acc4 * inv + b1v.x, acc5 * inv + b1v.y);
    __half2 o3 = __floats2half2_rn(acc6 * inv + b1v.z, acc7 * inv + b1v.w);
    *(uint4*)&g_h1f16[(size_t)w * D1 + lane * 8] =
        make_uint4(*(uint32_t*)&o0, *(uint32_t*)&o1, *(uint32_t*)&o2, *(uint32_t*)&o3);
}

// ---------------- layer-2 aggregation: single pass, fp16 gather, fp32 out ----------------
__global__ __launch_bounds__(256) void k_agg2(const float* __restrict__ bias,
                                              float* __restrict__ out) {
    int w = (blockIdx.x * blockDim.x + threadIdx.x) >> 5;
    int lane = threadIdx.x & 31;
    if (w >= NN) return;
    int start = g_rowptr[w], end = g_rowptr[w + 1];
    float ad = g_ad2[w];

    float den = 0.f;
    float acc0 = 0.f, acc1 = 0.f, acc2 = 0.f, acc3 = 0.f;
    int p = start;
    for (; p + 1 < end; p += 2) {
        int sA = g_esrc[p];
        int sB = g_esrc[p + 1];
        float lA = g_as2[sA];
        float lB = g_as2[sB];
        uint2 ua = *(const uint2*)&g_xh2h[(size_t)sA * D2 + lane * 4];
        uint2 ub = *(const uint2*)&g_xh2h[(size_t)sB * D2 + lane * 4];
        float gA = __expf(lrelu(lA + ad));
        float gB = __expf(lrelu(lB + ad));
        den += gA + gB;
        float2 a01 = __half22float2(*(__half2*)&ua.x);
        float2 a23 = __half22float2(*(__half2*)&ua.y);
        float2 b01 = __half22float2(*(__half2*)&ub.x);
        float2 b23 = __half22float2(*(__half2*)&ub.y);
        acc0 += gA * a01.x + gB * b01.x; acc1 += gA * a01.y + gB * b01.y;
        acc2 += gA * a23.x + gB * b23.x; acc3 += gA * a23.y + gB * b23.y;
    }
    if (p < end) {
        int sA = g_esrc[p];
        float gA = __expf(lrelu(g_as2[sA] + ad));
        uint2 ua = *(const uint2*)&g_xh2h[(size_t)sA * D2 + lane * 4];
        den += gA;
        float2 a01 = __half22float2(*(__half2*)&ua.x);
        float2 a23 = __half22float2(*(__half2*)&ua.y);
        acc0 += gA * a01.x; acc1 += gA * a01.y;
        acc2 += gA * a23.x; acc3 += gA * a23.y;
    }
    float inv = 1.0f / den;
    float4 b = *(const float4*)&bias[lane * 4];
    *(float4*)&out[(size_t)w * D2 + lane * 4] =
        make_float4(acc0 * inv + b.x, acc1 * inv + b.y, acc2 * inv + b.z, acc3 * inv + b.w);
}

// ---------------- host launch ----------------
extern "C" void kernel_launch(void* const* d_in, const int* in_sizes, int n_in,
                              void* d_out, int out_size) {
    const float* X    = (const float*)d_in[0];
    const int*   ei   = (const int*)  d_in[1];
    const float* W1   = (const float*)d_in[2];
    const float* as1  = (const float*)d_in[3];
    const float* ad1  = (const float*)d_in[4];
    const float* b1   = (const float*)d_in[5];
    const float* W2   = (const float*)d_in[6];
    const float* as2  = (const float*)d_in[7];
    const float* ad2  = (const float*)d_in[8];
    const float* b2   = (const float*)d_in[9];
    float* out = (float*)d_out;

    __half *p_xh1, *p_xh2, *p_xf, *p_h1f, *p_w1f, *p_w2f;
    cudaGetSymbolAddress((void**)&p_xh1, g_xh1h);
    cudaGetSymbolAddress((void**)&p_xh2, g_xh2h);
    cudaGetSymbolAddress((void**)&p_xf,  g_xf16);
    cudaGetSymbolAddress((void**)&p_h1f, g_h1f16);
    cudaGetSymbolAddress((void**)&p_w1f, g_wt1f);
    cudaGetSymbolAddress((void**)&p_w2f, g_wt2f);

    const int SMEM_GEMM = NSTAGE * 2 * TILE_ELEMS * 2;   // 61440 bytes
    cudaFuncSetAttribute(k_gemm_f16<64>,  cudaFuncAttributeMaxDynamicSharedMemorySize, SMEM_GEMM);
    cudaFuncSetAttribute(k_gemm_f16<256>, cudaFuncAttributeMaxDynamicSharedMemorySize, SMEM_GEMM);

    const int NODE_BLOCKS = (NN + 7) / 8;
    const int M_BLOCKS = (NN + 127) / 128;        // 391
    const int EDGE_BLOCKS = (ET + 255) / 256;
    const int PREP_BLOCKS = (NN * 16 + 255) / 256;

    // slot 3 = layer-1 GEMM (ncu-profiled launch)
    k_prep_count<<<PREP_BLOCKS, 256>>>(X, W1, W2, ei);                         // 0
    k_count<<<EDGE_BLOCKS, 256>>>(ei);                                         // 1
    k_scan_all<<<1, 1024>>>();                                                 // 2
    k_gemm_f16<64><<<dim3(D1 / 128, M_BLOCKS), 256, SMEM_GEMM>>>(p_xf, p_w1f, p_xh1, NN, D1); // 3
    k_fill<<<EDGE_BLOCKS, 256>>>(ei);                                          // 4
    k_attn1<<<NODE_BLOCKS, 256>>>(as1, ad1);                                   // 5
    k_agg1<<<NODE_BLOCKS, 256>>>(b1);                                          // 6
    k_gemm_f16<256><<<dim3(D2 / 128, M_BLOCKS), 256, SMEM_GEMM>>>(p_h1f, p_w2f, p_xh2, NN, D2); // 7
    k_attn2<<<NODE_BLOCKS, 256>>>(as2, ad2);                                   // 8
    k_agg2<<<NODE_BLOCKS, 256>>>(b2, out);                                     // 9
}

// round 13
// speedup vs baseline: 1.2453x; 1.2453x over previous
#include <cuda_runtime.h>
#include <cuda_bf16.h>
#include <cuda_fp16.h>
#include <cstdint>

#define NN 50000
#define NE 800000
#define ET 850000   // NE + NN self loops
#define D1 256      // heads(4) * h1(64)
#define D2 128

// ---------------- device scratch (static; no runtime allocation) ----------------
__device__ __align__(16) __half g_xh1h[NN * D1];   // X @ W1 (fp16)
__device__ __align__(16) __half g_xh2h[NN * D2];   // H1 @ W2 (fp16)
__device__ __align__(16) __half g_xf16[NN * 64];    // X as fp16 (gemm1 A)
__device__ __align__(16) __half g_h1f16[NN * D1];   // H1 as fp16 (gemm2 A)
__device__ __align__(16) float g_as1[NN * 4];
__device__ __align__(16) float g_ad1[NN * 4];
__device__ float g_as2[NN];
__device__ float g_ad2[NN];
__device__ int g_deg[NN];
__device__ int g_rowptr[NN + 1];
__device__ int g_rank[ET];
__device__ int g_esrc[ET];
__device__ int g_bsum[64];
// transposed fp16 weights: Wt[n][k]
__device__ __align__(16) __half g_wt1f[D1 * 64];
__device__ __align__(16) __half g_wt2f[D2 * D1];

__device__ __forceinline__ int esrc_of(const int* __restrict__ ei, int e) {
    return e < NE ? ei[e] : e - NE;
}
__device__ __forceinline__ int edst_of(const int* __restrict__ ei, int e) {
    return e < NE ? ei[NE + e] : e - NE;
}
__device__ __forceinline__ float lrelu(float x) { return x > 0.f ? x : 0.2f * x; }

// ---------------- fused prep: zero_deg + X fp16 + W1/W2 transpose fp16 ----------------
__global__ __launch_bounds__(256) void k_prep(const float* __restrict__ X,
                                              const float* __restrict__ W1,
                                              const float* __restrict__ W2) {
    int i = blockIdx.x * 256 + threadIdx.x;
    if (i < NN) g_deg[i] = 0;
    if (i < NN * 16) {
        float4 v = ((const float4*)X)[i];
        __half2 h0 = __floats2half2_rn(v.x, v.y);
        __half2 h1 = __floats2half2_rn(v.z, v.w);
        ((uint2*)g_xf16)[i] = make_uint2(*(uint32_t*)&h0, *(uint32_t*)&h1);
    }
    if (i < 64 * D1) {
        int k = i / D1, n = i % D1;
        g_wt1f[n * 64 + k] = __float2half(W1[i]);
    }
    if (i < D1 * D2) {
        int k = i / D2, n = i % D2;
        g_wt2f[n * D1 + k] = __float2half(W2[i]);
    }
}

// ---------------- CSR build (R11-proven) ----------------
__global__ void k_count(const int* __restrict__ ei) {
    int e = blockIdx.x * 256 + threadIdx.x;
    if (e < ET) {
        int r = atomicAdd(&g_deg[edst_of(ei, e)], 1);
        g_rank[e] = r;
    }
}

__global__ void k_scan1() {
    __shared__ int s[1024];
    int t = threadIdx.x;
    int i = blockIdx.x * 1024 + t;
    int v = (i < NN) ? g_deg[i] : 0;
    s[t] = v;
    __syncthreads();
    #pragma unroll
    for (int off = 1; off < 1024; off <<= 1) {
        int x = (t >= off) ? s[t - off] : 0;
        __syncthreads();
        s[t] += x;
        __syncthreads();
    }
    if (i < NN) g_rowptr[i] = s[t] - v;
    if (t == 1023) g_bsum[blockIdx.x] = s[t];
}

__global__ void k_scan2(int nblocks) {
    __shared__ int s[64];
    int t = threadIdx.x;
    int v = (t < nblocks) ? g_bsum[t] : 0;
    s[t] = v;
    __syncthreads();
    #pragma unroll
    for (int off = 1; off < 64; off <<= 1) {
        int x = (t >= off) ? s[t - off] : 0;
        __syncthreads();
        s[t] += x;
        __syncthreads();
    }
    if (t < nblocks) g_bsum[t] = s[t] - v;
}

__global__ void k_scan3() {
    int i = blockIdx.x * 1024 + threadIdx.x;
    if (i < NN)
        g_rowptr[i] = g_rowptr[i] + g_bsum[blockIdx.x];
    if (i == 0) g_rowptr[NN] = ET;
}

__global__ void k_fill(const int* __restrict__ ei) {
    int e = blockIdx.x * 256 + threadIdx.x;
    if (e < ET) {
        int d = edst_of(ei, e);
        int s = esrc_of(ei, e);
        g_esrc[g_rowptr[d] + g_rank[e]] = s;
    }
}

// ---------------- HMMA fp16 GEMM, 2-stage cp.async pipeline (R11-proven) ----------------
#define KC 32
#define ASTR 40
#define TILE_ELEMS (128 * ASTR)

__device__ __forceinline__ void ldsm4h(uint32_t& r0, uint32_t& r1, uint32_t& r2, uint32_t& r3,
                                       const __half* p) {
    uint32_t a = (uint32_t)__cvta_generic_to_shared(p);
    asm volatile("ldmatrix.sync.aligned.m8n8.x4.shared.b16 {%0,%1,%2,%3}, [%4];"
                 : "=r"(r0), "=r"(r1), "=r"(r2), "=r"(r3) : "r"(a));
}
__device__ __forceinline__ void mmaf16(float* d, uint32_t a0, uint32_t a1, uint32_t a2,
                                       uint32_t a3, uint32_t b0, uint32_t b1) {
    asm volatile(
        "mma.sync.aligned.m16n8k16.row.col.f32.f16.f16.f32 "
        "{%0,%1,%2,%3}, {%4,%5,%6,%7}, {%8,%9}, {%0,%1,%2,%3};"
        : "+f"(d[0]), "+f"(d[1]), "+f"(d[2]), "+f"(d[3])
        : "r"(a0), "r"(a1), "r"(a2), "r"(a3), "r"(b0), "r"(b1));
}
__device__ __forceinline__ void cpa16h(__half* dst, const __half* src) {
    uint32_t d = (uint32_t)__cvta_generic_to_shared(dst);
    asm volatile("cp.async.cg.shared.global [%0], [%1], 16;" :: "r"(d), "l"(src));
}

template<int KTOT>
__global__ __launch_bounds__(256, 2) void k_gemm_f16(const __half* __restrict__ A,
                                                     const __half* __restrict__ Bt,
                                                     __half* __restrict__ C,
                                                     int M, int NCOL) {
    constexpr int NCH = KTOT / KC;
    extern __shared__ __half smh[];

    int tid = threadIdx.x;
    int wid = tid >> 5, lane = tid & 31;
    int g = lane >> 2, tig = lane & 3;
    int wm = (wid >> 2) * 64;
    int wn = (wid & 3) * 32;
    int bm = blockIdx.y * 128;
    int bn = blockIdx.x * 128;

    float acc[4][4][4];
    #pragma unroll
    for (int mt = 0; mt < 4; mt++)
        #pragma unroll
        for (int nt = 0; nt < 4; nt++)
            #pragma unroll
            for (int f = 0; f < 4; f++) acc[mt][nt][f] = 0.f;

    int a_r = lane & 15, a_c = (lane >> 4) * 8;
    int b_r = (lane >> 4) * 8 + (lane & 7), b_c = ((lane >> 3) & 1) * 8;

    int frow0 = tid >> 2, fcol = (tid & 3) * 8;
    int frow1 = (tid + 256) >> 2;

    auto fill = [&](int s, int c) {
        __half* s_a = smh + (s * 2 + 0) * TILE_ELEMS;
        __half* s_b = smh + (s * 2 + 1) * TILE_ELEMS;
        int kbase = c * KC;
        int ar0 = bm + frow0; if (ar0 >= M) ar0 = M - 1;
        int ar1 = bm + frow1; if (ar1 >= M) ar1 = M - 1;
        cpa16h(&s_a[frow0 * ASTR + fcol], &A[(size_t)ar0 * KTOT + kbase + fcol]);
        cpa16h(&s_a[frow1 * ASTR + fcol], &A[(size_t)ar1 * KTOT + kbase + fcol]);
        cpa16h(&s_b[frow0 * ASTR + fcol], &Bt[(size_t)(bn + frow0) * KTOT + kbase + fcol]);
        cpa16h(&s_b[frow1 * ASTR + fcol], &Bt[(size_t)(bn + frow1) * KTOT + kbase + fcol]);
        asm volatile("cp.async.commit_group;");
    };

    fill(0, 0);
    int stage = 0;
    for (int c = 0; c < NCH; c++) {
        if (c + 1 < NCH) {
            fill(stage ^ 1, c + 1);
            asm volatile("cp.async.wait_group 1;");
        } else {
            asm volatile("cp.async.wait_group 0;");
        }
        __syncthreads();

        __half* s_a = smh + (stage * 2 + 0) * TILE_ELEMS;
        __half* s_b = smh + (stage * 2 + 1) * TILE_ELEMS;

        #pragma unroll
        for (int ks = 0; ks < KC; ks += 16) {
            uint32_t bf[4][2];
            #pragma unroll
            for (int p = 0; p < 2; p++)
                ldsm4h(bf[2*p][0], bf[2*p][1], bf[2*p+1][0], bf[2*p+1][1],
                       &s_b[(wn + p * 16 + b_r) * ASTR + ks + b_c]);
            #pragma unroll
            for (int mt = 0; mt < 4; mt++) {
                uint32_t a0, a1, a2, a3;
                ldsm4h(a0, a1, a2, a3, &s_a[(wm + mt * 16 + a_r) * ASTR + ks + a_c]);
                #pragma unroll
                for (int nt = 0; nt < 4; nt++)
                    mmaf16(acc[mt][nt], a0, a1, a2, a3, bf[nt][0], bf[nt][1]);
            }
        }
        __syncthreads();
        stage ^= 1;
    }

    #pragma unroll
    for (int mt = 0; mt < 4; mt++) {
        int r0 = bm + wm + mt * 16 + g;
        int r1 = r0 + 8;
        #pragma unroll
        for (int nt = 0; nt < 4; nt++) {
            int col = bn + wn + nt * 8 + 2 * tig;
            if (r0 < M) {
                __half2 h = __floats2half2_rn(acc[mt][nt][0], acc[mt][nt][1]);
                *(uint32_t*)&C[(size_t)r0 * NCOL + col] = *(uint32_t*)&h;
            }
            if (r1 < M) {
                __half2 h = __floats2half2_rn(acc[mt][nt][2], acc[mt][nt][3]);
                *(uint32_t*)&C[(size_t)r1 * NCOL + col] = *(uint32_t*)&h;
            }
        }
    }
}

// ---------------- attention logit vectors (fp16 features) ----------------
__global__ __launch_bounds__(256) void k_attn1(const float* __restrict__ att_s,
                                               const float* __restrict__ att_d) {
    int w = (blockIdx.x * blockDim.x + threadIdx.x) >> 5;
    int lane = threadIdx.x & 31;
    if (w >= NN) return;
    uint4 u = *(const uint4*)&g_xh1h[(size_t)w * D1 + lane * 8];
    float2 f0 = __half22float2(*(__half2*)&u.x);
    float2 f1 = __half22float2(*(__half2*)&u.y);
    float2 f2 = __half22float2(*(__half2*)&u.z);
    float2 f3 = __half22float2(*(__half2*)&u.w);
    const float4* ap = (const float4*)&att_s[lane * 8];
    float4 a0 = ap[0], a1 = ap[1];
    const float4* dp = (const float4*)&att_d[lane * 8];
    float4 d0 = dp[0], d1 = dp[1];
    float ss = f0.x*a0.x + f0.y*a0.y + f1.x*a0.z + f1.y*a0.w
             + f2.x*a1.x + f2.y*a1.y + f3.x*a1.z + f3.y*a1.w;
    float sd = f0.x*d0.x + f0.y*d0.y + f1.x*d0.z + f1.y*d0.w
             + f2.x*d1.x + f2.y*d1.y + f3.x*d1.z + f3.y*d1.w;
    #pragma unroll
    for (int m = 1; m < 8; m <<= 1) {
        ss += __shfl_xor_sync(0xffffffffu, ss, m);
        sd += __shfl_xor_sync(0xffffffffu, sd, m);
    }
    if ((lane & 7) == 0) {
        int h = lane >> 3;
        g_as1[w * 4 + h] = ss;
        g_ad1[w * 4 + h] = sd;
    }
}

__global__ __launch_bounds__(256) void k_attn2(const float* __restrict__ att_s,
                                               const float* __restrict__ att_d) {
    int w = (blockIdx.x * blockDim.x + threadIdx.x) >> 5;
    int lane = threadIdx.x & 31;
    if (w >= NN) return;
    uint2 u = *(const uint2*)&g_xh2h[(size_t)w * D2 + lane * 4];
    float2 f0 = __half22float2(*(__half2*)&u.x);
    float2 f1 = __half22float2(*(__half2*)&u.y);
    float4 a = *(const float4*)&att_s[lane * 4];
    float4 d = *(const float4*)&att_d[lane * 4];
    float ss = f0.x*a.x + f0.y*a.y + f1.x*a.z + f1.y*a.w;
    float sd = f0.x*d.x + f0.y*d.y + f1.x*d.z + f1.y*d.w;
    #pragma unroll
    for (int m = 1; m < 32; m <<= 1) {
        ss += __shfl_xor_sync(0xffffffffu, ss, m);
        sd += __shfl_xor_sync(0xffffffffu, sd, m);
    }
    if (lane == 0) { g_as2[w] = ss; g_ad2[w] = sd; }
}

// ---------------- layer-1 aggregation: single pass, fp16 gather, fp16 H1 out ----------------
__global__ __launch_bounds__(256) void k_agg1(const float* __restrict__ bias) {
    int w = (blockIdx.x * blockDim.x + threadIdx.x) >> 5;
    int lane = threadIdx.x & 31;
    if (w >= NN) return;
    int start = g_rowptr[w], end = g_rowptr[w + 1];
    int head = lane >> 3;
    float4 ad4 = *(const float4*)&g_ad1[w * 4];
    float adh = (head == 0) ? ad4.x : (head == 1) ? ad4.y : (head == 2) ? ad4.z : ad4.w;

    float den = 0.f;
    float acc0 = 0.f, acc1 = 0.f, acc2 = 0.f, acc3 = 0.f;
    float acc4 = 0.f, acc5 = 0.f, acc6 = 0.f, acc7 = 0.f;
    int p = start;
    for (; p + 1 < end; p += 2) {
        int sA = g_esrc[p];
        int sB = g_esrc[p + 1];
        float lA = g_as1[sA * 4 + head];
        float lB = g_as1[sB * 4 + head];
        uint4 ua = *(const uint4*)&g_xh1h[(size_t)sA * D1 + lane * 8];
        uint4 ub = *(const uint4*)&g_xh1h[(size_t)sB * D1 + lane * 8];
        float gA = __expf(lrelu(lA + adh));
        float gB = __expf(lrelu(lB + adh));
        den += gA + gB;
        float2 a0 = __half22float2(*(__half2*)&ua.x);
        float2 a1 = __half22float2(*(__half2*)&ua.y);
        float2 a2 = __half22float2(*(__half2*)&ua.z);
        float2 a3 = __half22float2(*(__half2*)&ua.w);
        float2 b0 = __half22float2(*(__half2*)&ub.x);
        float2 b1 = __half22float2(*(__half2*)&ub.y);
        float2 b2 = __half22float2(*(__half2*)&ub.z);
        float2 b3 = __half22float2(*(__half2*)&ub.w);
        acc0 += gA * a0.x + gB * b0.x; acc1 += gA * a0.y + gB * b0.y;
        acc2 += gA * a1.x + gB * b1.x; acc3 += gA * a1.y + gB * b1.y;
        acc4 += gA * a2.x + gB * b2.x; acc5 += gA * a2.y + gB * b2.y;
        acc6 += gA * a3.x + gB * b3.x; acc7 += gA * a3.y + gB * b3.y;
    }
    if (p < end) {
        int sA = g_esrc[p];
        float gA = __expf(lrelu(g_as1[sA * 4 + head] + adh));
        uint4 ua = *(const uint4*)&g_xh1h[(size_t)sA * D1 + lane * 8];
        den += gA;
        float2 a0 = __half22float2(*(__half2*)&ua.x);
        float2 a1 = __half22float2(*(__half2*)&ua.y);
        float2 a2 = __half22float2(*(__half2*)&ua.z);
        float2 a3 = __half22float2(*(__half2*)&ua.w);
        acc0 += gA * a0.x; acc1 += gA * a0.y;
        acc2 += gA * a1.x; acc3 += gA * a1.y;
        acc4 += gA * a2.x; acc5 += gA * a2.y;
        acc6 += gA * a3.x; acc7 += gA * a3.y;
    }
    float inv = 1.0f / den;
    const float4* bp = (const float4*)&bias[lane * 8];
    float4 b0 = bp[0], b1v = bp[1];
    __half2 o0 = __floats2half2_rn(acc0 * inv + b0.x,  acc1 * inv + b0.y);
    __half2 o1 = __floats2half2_rn(acc2 * inv + b0.z,  acc3 * inv + b0.w);
    __half2 o2 = __floats2half2_rn(acc4 * inv + b1v.x, acc5 * inv + b1v.y);
    __half2 o3 = __floats2half2_rn(acc6 * inv + b1v.z, acc7 * inv + b1v.w);
    *(uint4*)&g_h1f16[(size_t)w * D1 + lane * 8] =
        make_uint4(*(uint32_t*)&o0, *(uint32_t*)&o1, *(uint32_t*)&o2, *(uint32_t*)&o3);
}

// ---------------- layer-2 aggregation: single pass, fp16 gather, fp32 out ----------------
__global__ __launch_bounds__(256) void k_agg2(const float* __restrict__ bias,
                                              float* __restrict__ out) {
    int w = (blockIdx.x * blockDim.x + threadIdx.x) >> 5;
    int lane = threadIdx.x & 31;
    if (w >= NN) return;
    int start = g_rowptr[w], end = g_rowptr[w + 1];
    float ad = g_ad2[w];

    float den = 0.f;
    float acc0 = 0.f, acc1 = 0.f, acc2 = 0.f, acc3 = 0.f;
    int p = start;
    for (; p + 1 < end; p += 2) {
        int sA = g_esrc[p];
        int sB = g_esrc[p + 1];
        float lA = g_as2[sA];
        float lB = g_as2[sB];
        uint2 ua = *(const uint2*)&g_xh2h[(size_t)sA * D2 + lane * 4];
        uint2 ub = *(const uint2*)&g_xh2h[(size_t)sB * D2 + lane * 4];
        float gA = __expf(lrelu(lA + ad));
        float gB = __expf(lrelu(lB + ad));
        den += gA + gB;
        float2 a01 = __half22float2(*(__half2*)&ua.x);
        float2 a23 = __half22float2(*(__half2*)&ua.y);
        float2 b01 = __half22float2(*(__half2*)&ub.x);
        float2 b23 = __half22float2(*(__half2*)&ub.y);
        acc0 += gA * a01.x + gB * b01.x; acc1 += gA * a01.y + gB * b01.y;
        acc2 += gA * a23.x + gB * b23.x; acc3 += gA * a23.y + gB * b23.y;
    }
    if (p < end) {
        int sA = g_esrc[p];
        float gA = __expf(lrelu(g_as2[sA] + ad));
        uint2 ua = *(const uint2*)&g_xh2h[(size_t)sA * D2 + lane * 4];
        den += gA;
        float2 a01 = __half22float2(*(__half2*)&ua.x);
        float2 a23 = __half22float2(*(__half2*)&ua.y);
        acc0 += gA * a01.x; acc1 += gA * a01.y;
        acc2 += gA * a23.x; acc3 += gA * a23.y;
    }
    float inv = 1.0f / den;
    float4 b = *(const float4*)&bias[lane * 4];
    *(float4*)&out[(size_t)w * D2 + lane * 4] =
        make_float4(acc0 * inv + b.x, acc1 * inv + b.y, acc2 * inv + b.z, acc3 * inv + b.w);
}

// ---------------- host launch ----------------
extern "C" void kernel_launch(void* const* d_in, const int* in_sizes, int n_in,
                              void* d_out, int out_size) {
    const float* X    = (const float*)d_in[0];
    const int*   ei   = (const int*)  d_in[1];
    const float* W1   = (const float*)d_in[2];
    const float* as1  = (const float*)d_in[3];
    const float* ad1  = (const float*)d_in[4];
    const float* b1   = (const float*)d_in[5];
    const float* W2   = (const float*)d_in[6];
    const float* as2  = (const float*)d_in[7];
    const float* ad2  = (const float*)d_in[8];
    const float* b2   = (const float*)d_in[9];
    float* out = (float*)d_out;

    __half *p_xh1, *p_xh2, *p_xf, *p_h1f, *p_w1f, *p_w2f;
    cudaGetSymbolAddress((void**)&p_xh1, g_xh1h);
    cudaGetSymbolAddress((void**)&p_xh2, g_xh2h);
    cudaGetSymbolAddress((void**)&p_xf,  g_xf16);
    cudaGetSymbolAddress((void**)&p_h1f, g_h1f16);
    cudaGetSymbolAddress((void**)&p_w1f, g_wt1f);
    cudaGetSymbolAddress((void**)&p_w2f, g_wt2f);

    const int SMEM_GEMM = 2 * 2 * TILE_ELEMS * 2;   // 40960 bytes
    cudaFuncSetAttribute(k_gemm_f16<64>,  cudaFuncAttributeMaxDynamicSharedMemorySize, SMEM_GEMM);
    cudaFuncSetAttribute(k_gemm_f16<256>, cudaFuncAttributeMaxDynamicSharedMemorySize, SMEM_GEMM);

    const int SCAN_BLOCKS = (NN + 1023) / 1024;   // 49
    const int NODE_BLOCKS = (NN + 7) / 8;
    const int M_BLOCKS = (NN + 127) / 128;        // 391
    const int EDGE_BLOCKS = (ET + 255) / 256;
    const int PREP_BLOCKS = (NN * 16 + 255) / 256;

    // Fork a side stream for the CSR branch so it overlaps gemm1+attn1.
    cudaStream_t s2;
    cudaStreamCreate(&s2);
    cudaEvent_t evFork, evJoin;
    cudaEventCreateWithFlags(&evFork, cudaEventDisableTiming);
    cudaEventCreateWithFlags(&evJoin, cudaEventDisableTiming);

    // main stream: prep (zeroes g_deg, converts X/W)
    k_prep<<<PREP_BLOCKS, 256>>>(X, W1, W2);
    cudaEventRecord(evFork, 0);
    cudaStreamWaitEvent(s2, evFork, 0);

    // side stream: CSR build chain
    k_count<<<EDGE_BLOCKS, 256, 0, s2>>>(ei);
    k_scan1<<<SCAN_BLOCKS, 1024, 0, s2>>>();
    k_scan2<<<1, 64, 0, s2>>>(SCAN_BLOCKS);
    k_scan3<<<SCAN_BLOCKS, 1024, 0, s2>>>();
    k_fill<<<EDGE_BLOCKS, 256, 0, s2>>>(ei);
    cudaEventRecord(evJoin, s2);

    // main stream: gemm1 -> attn1 (independent of CSR)
    k_gemm_f16<64><<<dim3(D1 / 128, M_BLOCKS), 256, SMEM_GEMM>>>(p_xf, p_w1f, p_xh1, NN, D1);
    k_attn1<<<NODE_BLOCKS, 256>>>(as1, ad1);

    // join: agg1 needs CSR + attn1
    cudaStreamWaitEvent(0, evJoin, 0);
    k_agg1<<<NODE_BLOCKS, 256>>>(b1);
    k_gemm_f16<256><<<dim3(D2 / 128, M_BLOCKS), 256, SMEM_GEMM>>>(p_h1f, p_w2f, p_xh2, NN, D2);
    k_attn2<<<NODE_BLOCKS, 256>>>(as2, ad2);
    k_agg2<<<NODE_BLOCKS, 256>>>(b2, out);

    cudaEventDestroy(evFork);
    cudaEventDestroy(evJoin);
    cudaStreamDestroy(s2);
}